// round 5
// baseline (speedup 1.0000x reference)
#include <cuda_runtime.h>
#include <cstdint>

// Problem dims
#define B_   512
#define T_   1024
#define D_   64
#define H_   256
#define O_   64

#define ROWS 4
#define NCTA (B_/ROWS)     // 128 CTAs
#define NTHR 256           // thread j owns hidden unit j
#define KC   148           // k-slices of Wh cached in SMEM
#define KCC  (KC/4)        // 37 chunks of 4
#define KS   ((H_-KC)/4)   // 27 streamed chunks
#define PF   9             // L2 prefetch depth (27 = 3*9)

// Scratch (allocation-free rule: static __device__ arrays)
__device__ float g_Wh2[H_*H_];   // Wh packed [k/4][j][4]   (256 KB)
__device__ float g_Wx2[D_*H_];   // Wx packed [d/4][j][4]   ( 64 KB)

// fma.rn.f32x2 — packed dual fp32 FMA (not emitted by ptxas from C++)
__device__ __forceinline__ unsigned long long fma2(unsigned long long a,
                                                   unsigned long long b,
                                                   unsigned long long c) {
    unsigned long long d;
    asm("fma.rn.f32x2 %0, %1, %2, %3;" : "=l"(d) : "l"(a), "l"(b), "l"(c));
    return d;
}

// Repack Wf[H, D+H] into coalesced LDG.128/LDS.128-friendly layouts.
__global__ void ltc_prep_kernel(const float* __restrict__ Wf) {
    int i = blockIdx.x * blockDim.x + threadIdx.x;
    if (i < H_*H_) {
        int c = i >> 10, rem = i & 1023;
        int j = rem >> 2, s = rem & 3;
        int k = c * 4 + s;
        g_Wh2[i] = Wf[j * (D_ + H_) + D_ + k];
    }
    int i2 = i - H_*H_;
    if (i2 >= 0 && i2 < D_*H_) {
        int c = i2 >> 10, rem = i2 & 1023;
        int j = rem >> 2, s = rem & 3;
        int d = c * 4 + s;
        g_Wx2[i2] = Wf[j * (D_ + H_) + d];
    }
}

// SMEM layout (floats):
//   s_wx  [0, 16384)              Wx packed
//   s_wh  [16384, 16384+37888)    cached Wh (first KC k-slices)
//   s_h   [.., +2048)             h double buffer: [buf][r][k]
//   s_x   [.., +512)              x double buffer: [buf][r*64+d]
#define SMEM_FLOATS (D_*H_ + KCC*1024 + 2*ROWS*H_ + 2*ROWS*D_)

__global__ __launch_bounds__(NTHR, 1)
void ltc_main_kernel(const float* __restrict__ x,
                     const float* __restrict__ bf,
                     const float* __restrict__ tau,
                     const float* __restrict__ A,
                     const float* __restrict__ Wo,
                     const float* __restrict__ bo,
                     float* __restrict__ out)
{
    extern __shared__ float sm[];
    float* s_wx = sm;
    float* s_wh = sm + D_*H_;
    float* s_h  = s_wh + KCC*1024;
    float* s_x  = s_h + 2*ROWS*H_;

    const int tid  = threadIdx.x;
    const int j    = tid;
    const int row0 = blockIdx.x * ROWS;

    // ---- stage weights into SMEM (float4 copies) ----
    {
        float4*       dw = reinterpret_cast<float4*>(s_wx);
        const float4* sw = reinterpret_cast<const float4*>(g_Wx2);
        for (int i = tid; i < (D_*H_)/4; i += NTHR) dw[i] = sw[i];
        float4*       dh = reinterpret_cast<float4*>(s_wh);
        const float4* sh = reinterpret_cast<const float4*>(g_Wh2);
        for (int i = tid; i < (KCC*1024)/4; i += NTHR) dh[i] = sh[i];
    }

    // ---- init state ----
#pragma unroll
    for (int r = 0; r < ROWS; r++) s_h[r*H_ + tid] = 0.0f;

    const int rx = tid >> 6, dx = tid & 63;
    const float* xrow = x + (size_t)(row0 + rx) * T_ * D_ + dx;
    s_x[tid] = xrow[0];  // x at t=0

    const float bfj = bf[j];
    const float itj = 1.0f / expf(tau[j]);
    const float Aj  = A[j];
    float hreg[ROWS] = {0.f, 0.f, 0.f, 0.f};

    // streamed-Wh base pointer for this thread's column j
    const ulonglong2* gw =
        reinterpret_cast<const ulonglong2*>(g_Wh2 + KCC*1024 + (j << 2));

    __syncthreads();

    // ================= recurrent loop =================
    for (int t = 0; t < T_; ++t) {
        const float* hb = s_h + (t & 1) * (ROWS*H_);
        const float* xb = s_x + (t & 1) * (ROWS*D_);
        float*       hn = s_h + ((t + 1) & 1) * (ROWS*H_);
        float*       xn = s_x + ((t + 1) & 1) * (ROWS*D_);

        // kick off streamed-Wh prefetch ring early (lands under cached compute)
        ulonglong2 wpre[PF];
#pragma unroll
        for (int p = 0; p < PF; p++) wpre[p] = gw[p * 256];

        // prefetch next timestep's x
        float x_next = 0.0f;
        if (t + 1 < T_) x_next = xrow[(t + 1) * D_];

        unsigned long long acc[ROWS] = {0ull, 0ull, 0ull, 0ull};

        // ---- x-projection part: 64 inputs ----
#pragma unroll
        for (int c = 0; c < D_/4; c++) {
            ulonglong2 w  = *reinterpret_cast<const ulonglong2*>(s_wx + c*1024 + (j << 2));
            ulonglong2 v0 = *reinterpret_cast<const ulonglong2*>(xb + 0*D_ + c*4);
            ulonglong2 v1 = *reinterpret_cast<const ulonglong2*>(xb + 1*D_ + c*4);
            ulonglong2 v2 = *reinterpret_cast<const ulonglong2*>(xb + 2*D_ + c*4);
            ulonglong2 v3 = *reinterpret_cast<const ulonglong2*>(xb + 3*D_ + c*4);
            acc[0] = fma2(w.x, v0.x, acc[0]); acc[0] = fma2(w.y, v0.y, acc[0]);
            acc[1] = fma2(w.x, v1.x, acc[1]); acc[1] = fma2(w.y, v1.y, acc[1]);
            acc[2] = fma2(w.x, v2.x, acc[2]); acc[2] = fma2(w.y, v2.y, acc[2]);
            acc[3] = fma2(w.x, v3.x, acc[3]); acc[3] = fma2(w.y, v3.y, acc[3]);
        }

        // ---- recurrent part, SMEM-cached k in [0, KC) ----
#pragma unroll
        for (int c = 0; c < KCC; c++) {
            ulonglong2 w  = *reinterpret_cast<const ulonglong2*>(s_wh + c*1024 + (j << 2));
            ulonglong2 v0 = *reinterpret_cast<const ulonglong2*>(hb + 0*H_ + c*4);
            ulonglong2 v1 = *reinterpret_cast<const ulonglong2*>(hb + 1*H_ + c*4);
            ulonglong2 v2 = *reinterpret_cast<const ulonglong2*>(hb + 2*H_ + c*4);
            ulonglong2 v3 = *reinterpret_cast<const ulonglong2*>(hb + 3*H_ + c*4);
            acc[0] = fma2(w.x, v0.x, acc[0]); acc[0] = fma2(w.y, v0.y, acc[0]);
            acc[1] = fma2(w.x, v1.x, acc[1]); acc[1] = fma2(w.y, v1.y, acc[1]);
            acc[2] = fma2(w.x, v2.x, acc[2]); acc[2] = fma2(w.y, v2.y, acc[2]);
            acc[3] = fma2(w.x, v3.x, acc[3]); acc[3] = fma2(w.y, v3.y, acc[3]);
        }

        // ---- recurrent part, L2-streamed k in [KC, 256) ----
#pragma unroll
        for (int c = 0; c < KS; c++) {
            ulonglong2 w = wpre[c % PF];
            if (c + PF < KS) wpre[c % PF] = gw[(c + PF) * 256];
            const int kk = KC + c*4;
            ulonglong2 v0 = *reinterpret_cast<const ulonglong2*>(hb + 0*H_ + kk);
            ulonglong2 v1 = *reinterpret_cast<const ulonglong2*>(hb + 1*H_ + kk);
            ulonglong2 v2 = *reinterpret_cast<const ulonglong2*>(hb + 2*H_ + kk);
            ulonglong2 v3 = *reinterpret_cast<const ulonglong2*>(hb + 3*H_ + kk);
            acc[0] = fma2(w.x, v0.x, acc[0]); acc[0] = fma2(w.y, v0.y, acc[0]);
            acc[1] = fma2(w.x, v1.x, acc[1]); acc[1] = fma2(w.y, v1.y, acc[1]);
            acc[2] = fma2(w.x, v2.x, acc[2]); acc[2] = fma2(w.y, v2.y, acc[2]);
            acc[3] = fma2(w.x, v3.x, acc[3]); acc[3] = fma2(w.y, v3.y, acc[3]);
        }

        // ---- gate + state update ----
#pragma unroll
        for (int r = 0; r < ROWS; r++) {
            unsigned long long a = acc[r];
            float z = __uint_as_float((unsigned)a)
                    + __uint_as_float((unsigned)(a >> 32)) + bfj;
            float e = __expf(-z);
            float f = __fdividef(1.0f, 1.0f + e);
            float h = hreg[r];
            float dh = (-(itj + f) * h + f * Aj) * 0.1f;
            h += dh;
            hreg[r] = h;
            hn[r*H_ + j] = h;
        }
        xn[tid] = x_next;
        __syncthreads();
    }

    // ================= output projection =================
    // h_final lives in buffer (T_ & 1) == 0
    {
        const float* hf = s_h + (T_ & 1) * (ROWS*H_);
        const int r = tid >> 6, o = tid & 63;
        const float4* wo4 = reinterpret_cast<const float4*>(Wo + o*H_);
        const float4* hf4 = reinterpret_cast<const float4*>(hf + r*H_);
        float s = 0.0f;
#pragma unroll
        for (int q = 0; q < H_/4; q++) {
            float4 w = wo4[q];
            float4 h = hf4[q];
            s += w.x*h.x + w.y*h.y + w.z*h.z + w.w*h.w;
        }
        out[(row0 + r)*O_ + o] = s + bo[o];
    }
}

extern "C" void kernel_launch(void* const* d_in, const int* in_sizes, int n_in,
                              void* d_out, int out_size)
{
    (void)in_sizes; (void)n_in; (void)out_size;
    const float* x   = (const float*)d_in[0];
    const float* Wf  = (const float*)d_in[1];
    const float* bf  = (const float*)d_in[2];
    const float* tau = (const float*)d_in[3];
    const float* A   = (const float*)d_in[4];
    const float* Wo  = (const float*)d_in[5];
    const float* bo  = (const float*)d_in[6];
    float* out = (float*)d_out;

    const int smem_bytes = SMEM_FLOATS * (int)sizeof(float);  // 227,328 B
    cudaFuncSetAttribute(ltc_main_kernel,
                         cudaFuncAttributeMaxDynamicSharedMemorySize, smem_bytes);

    const int prep_elems = H_*H_ + D_*H_;  // 81920
    ltc_prep_kernel<<<(prep_elems + NTHR - 1) / NTHR, NTHR>>>(Wf);
    ltc_main_kernel<<<NCTA, NTHR, smem_bytes>>>(x, bf, tau, A, Wo, bo, out);
}